// round 15
// baseline (speedup 1.0000x reference)
#include <cuda_runtime.h>
#include <cuda_bf16.h>
#include <stdint.h>

// ============================================================================
// QLSTM  (SEQ=2048, B=64, D=512, H=512)
// Phase 0: pack weights; split x and Wx into bf16 hi/lo
// Phase 1: mma.sync (bf16, f32-accum) split GEMM, virtual K=1536:
//            Gx = x_hi@Wh^T + x_hi@Wl^T + x_lo@Wh^T + b
//          output layout g_Gx[t][gategroup(128)][b(64)][16]
// Phase 2: persistent LSTM, 128 CTAs, counter grid-barrier per step
//          (round-10 passing kernel, verbatim)
// NOTE: no tcgen05 anywhere — harness PTX target is sm_103 (no 'a'), which
// rejects tcgen05; mma.sync m16n8k16 is compute_80+ and legal.
// ============================================================================

typedef unsigned long long ull;

#define SEQ   2048
#define BATCH 64
#define DIN   512
#define HID   512
#define NGATE 2048
#define M_TOT (SEQ * BATCH)

// ---- device scratch --------------------------------------------------------
__device__ float g_Gx[(size_t)M_TOT * NGATE];          // 1 GiB
__device__ __nv_bfloat16 g_x_hi[(size_t)M_TOT * DIN];
__device__ __nv_bfloat16 g_x_lo[(size_t)M_TOT * DIN];
__device__ __nv_bfloat16 g_Wx_hi[NGATE * DIN];         // [n][k]
__device__ __nv_bfloat16 g_Wx_lo[NGATE * DIN];         // [n][k]
__device__ float g_Whp[NGATE * HID];                   // [n][k] hidden half
__device__ float g_bpack[NGATE];
__device__ float g_hT[2 * HID * BATCH];                // double-buffered h [jg][b]
__device__ unsigned g_bar;

// ---- scalar helpers --------------------------------------------------------
__device__ __forceinline__ void ffma2(ull& d, ull a, ull b) {
    asm("fma.rn.f32x2 %0, %1, %2, %0;" : "+l"(d) : "l"(a), "l"(b));
}
__device__ __forceinline__ ull pack2(float x) {
    ull r;
    asm("mov.b64 %0, {%1, %1};" : "=l"(r) : "f"(x));
    return r;
}
__device__ __forceinline__ float sigmoidf_(float x) {
    return __fdividef(1.0f, 1.0f + __expf(-x));
}
__device__ __forceinline__ float tanhf_(float x) {
    return 1.0f - __fdividef(2.0f, __expf(2.0f * x) + 1.0f);
}

// ---- cp.async wrappers -----------------------------------------------------
__device__ __forceinline__ uint32_t smem_u32(const void* p) {
    uint32_t a;
    asm("{ .reg .u64 t; cvta.to.shared.u64 t, %1; cvt.u32.u64 %0, t; }"
        : "=r"(a) : "l"(p));
    return a;
}
__device__ __forceinline__ void cp16(uint32_t dst, const void* src) {
    asm volatile("cp.async.cg.shared.global [%0], [%1], 16;"
                 :: "r"(dst), "l"(src) : "memory");
}
__device__ __forceinline__ void cp_commit() {
    asm volatile("cp.async.commit_group;" ::: "memory");
}
__device__ __forceinline__ void cp_wait0() {
    asm volatile("cp.async.wait_group 0;" ::: "memory");
}
__device__ __forceinline__ void cp_wait1() {
    asm volatile("cp.async.wait_group 1;" ::: "memory");
}

// ---- mma.sync m16n8k16 bf16 -> f32 ----------------------------------------
__device__ __forceinline__ void mma16816(float& c0, float& c1, float& c2, float& c3,
                                         uint32_t a0, uint32_t a1, uint32_t a2,
                                         uint32_t a3, uint32_t b0, uint32_t b1) {
    asm volatile(
        "mma.sync.aligned.m16n8k16.row.col.f32.bf16.bf16.f32 "
        "{%0,%1,%2,%3}, {%4,%5,%6,%7}, {%8,%9}, {%0,%1,%2,%3};"
        : "+f"(c0), "+f"(c1), "+f"(c2), "+f"(c3)
        : "r"(a0), "r"(a1), "r"(a2), "r"(a3), "r"(b0), "r"(b1));
}

// ============================================================================
__global__ void qlstm_reset() {
    if (threadIdx.x == 0) g_bar = 0u;
}

// ============================================================================
// Phase 0: weight pack + bf16 split of the input-half weights
// ============================================================================
__global__ void qlstm_pack(const float* __restrict__ Wf, const float* __restrict__ bf,
                           const float* __restrict__ Wi, const float* __restrict__ bi,
                           const float* __restrict__ Wg, const float* __restrict__ bg,
                           const float* __restrict__ Wo, const float* __restrict__ bo) {
    const float* Ws[4] = {Wf, Wi, Wg, Wo};
    const float* bs[4] = {bf, bi, bg, bo};
    const int stride = gridDim.x * blockDim.x;
    const int idx = blockIdx.x * blockDim.x + threadIdx.x;

    for (int i = idx; i < NGATE * DIN; i += stride) {   // Wx hi/lo [n][k]
        int k = i & (DIN - 1);
        int n = i >> 9;
        int j = n >> 2;
        int g = n & 3;
        float w = Ws[g][j * (DIN + HID) + k];
        __nv_bfloat16 hi = __float2bfloat16(w);
        __nv_bfloat16 lo = __float2bfloat16(w - __bfloat162float(hi));
        g_Wx_hi[i] = hi;
        g_Wx_lo[i] = lo;
    }
    for (int i = idx; i < NGATE * HID; i += stride) {   // Whp [n][k] fp32
        int k = i & (HID - 1);
        int n = i >> 9;
        int j = n >> 2;
        int g = n & 3;
        g_Whp[i] = Ws[g][j * (DIN + HID) + DIN + k];
    }
    for (int i = idx; i < NGATE; i += stride) {
        int j = i >> 2;
        int g = i & 3;
        g_bpack[i] = bs[g][j];
    }
}

// ============================================================================
// Phase 0c: split x into bf16 hi/lo
// ============================================================================
__global__ void qlstm_splitx(const float* __restrict__ x) {
    const size_t n2 = (size_t)M_TOT * DIN / 2;
    const size_t stride = (size_t)gridDim.x * blockDim.x;
    for (size_t i = blockIdx.x * (size_t)blockDim.x + threadIdx.x; i < n2; i += stride) {
        float2 v = ((const float2*)x)[i];
        __nv_bfloat16 h0 = __float2bfloat16(v.x);
        __nv_bfloat16 h1 = __float2bfloat16(v.y);
        __nv_bfloat162 hp;
        hp.x = h0;
        hp.y = h1;
        __nv_bfloat162 lp;
        lp.x = __float2bfloat16(v.x - __bfloat162float(h0));
        lp.y = __float2bfloat16(v.y - __bfloat162float(h1));
        ((__nv_bfloat162*)g_x_hi)[i] = hp;
        ((__nv_bfloat162*)g_x_lo)[i] = lp;
    }
}

// ============================================================================
// Phase 1: mma.sync bf16-split GEMM.
// C[m=131072][n=2048], virtual K = 1536 (48 chunks of 32):
//   chunks  0-15: x_hi * W_hi,  16-31: x_hi * W_lo,  32-47: x_lo * W_hi
// CTA 128x128, 256 thr (8 warps, 64x32 warp tiles), 3-stage cp.async pipe.
// Tiles row-major [row][32] bf16 with 80B pitch (conflict-free frag loads).
// ============================================================================
#define P1_PITCH  80                      // bytes per tile row (40 bf16)
#define P1_ATILE  10240                   // 128 * 80
#define P1_STAGE  20480                   // A + B
#define P1_SMEM   61440                   // 3 stages

__device__ __forceinline__ void p1_load(uint32_t sb, int slot, int c,
                                        int m0, int n0, int tid) {
    const int term = c >> 4;
    const int kc = c & 15;
    const __nv_bfloat16* As = (term == 2) ? g_x_lo : g_x_hi;
    const __nv_bfloat16* Bs = (term == 1) ? g_Wx_lo : g_Wx_hi;
    const uint32_t stb = sb + slot * P1_STAGE;
    {   // A: idx = tid, tid+256  (512 cp16 total)
        int idx = tid;
        int row = idx >> 2, u = idx & 3;
        cp16(stb + row * P1_PITCH + u * 16,
             As + (size_t)(m0 + row) * DIN + kc * 32 + u * 8);
        idx = tid + 256;
        row = idx >> 2;
        u = idx & 3;
        cp16(stb + row * P1_PITCH + u * 16,
             As + (size_t)(m0 + row) * DIN + kc * 32 + u * 8);
    }
    {   // B
        int idx = tid;
        int row = idx >> 2, u = idx & 3;
        cp16(stb + P1_ATILE + row * P1_PITCH + u * 16,
             Bs + (size_t)(n0 + row) * DIN + kc * 32 + u * 8);
        idx = tid + 256;
        row = idx >> 2;
        u = idx & 3;
        cp16(stb + P1_ATILE + row * P1_PITCH + u * 16,
             Bs + (size_t)(n0 + row) * DIN + kc * 32 + u * 8);
    }
}

__global__ void __launch_bounds__(256, 2)
qlstm_gemm_mma() {
    extern __shared__ char smg[];
    const uint32_t sb = smem_u32(smg);
    const int tid = threadIdx.x;
    const int wid = tid >> 5;
    const int lane = tid & 31;
    const int groupid = lane >> 2;
    const int tig = lane & 3;
    const int n0 = blockIdx.x * 128;
    const int m0 = blockIdx.y * 128;
    const int warpM = (wid & 1) * 64;
    const int warpN = (wid >> 1) * 32;

    float acc[4][4][4];
#pragma unroll
    for (int i = 0; i < 4; i++)
#pragma unroll
        for (int j = 0; j < 4; j++)
#pragma unroll
            for (int q = 0; q < 4; q++) acc[i][j][q] = 0.0f;

    p1_load(sb, 0, 0, m0, n0, tid);
    cp_commit();
    p1_load(sb, 1, 1, m0, n0, tid);
    cp_commit();

    const int aoff = (warpM + groupid) * P1_PITCH + tig * 4;
    const int boff = P1_ATILE + (warpN + groupid) * P1_PITCH + tig * 4;

    for (int c = 0; c < 48; c++) {
        if (c + 2 < 48) cp_wait1();
        else cp_wait0();
        __syncthreads();
        if (c + 2 < 48) {
            p1_load(sb, (c + 2) % 3, c + 2, m0, n0, tid);
            cp_commit();
        }

        const char* st = smg + (c % 3) * P1_STAGE;
        const char* sA = st + aoff;
        const char* sB = st + boff;
#pragma unroll
        for (int ks = 0; ks < 2; ks++) {
            const int kb = ks * 32;                 // byte offset of k-step
            uint32_t b0[4], b1[4];
#pragma unroll
            for (int nf = 0; nf < 4; nf++) {
                b0[nf] = *(const uint32_t*)(sB + nf * 640 + kb);
                b1[nf] = *(const uint32_t*)(sB + nf * 640 + kb + 16);
            }
#pragma unroll
            for (int mf = 0; mf < 4; mf++) {
                uint32_t a0 = *(const uint32_t*)(sA + mf * 1280 + kb);
                uint32_t a1 = *(const uint32_t*)(sA + mf * 1280 + 640 + kb);
                uint32_t a2 = *(const uint32_t*)(sA + mf * 1280 + kb + 16);
                uint32_t a3 = *(const uint32_t*)(sA + mf * 1280 + 640 + kb + 16);
#pragma unroll
                for (int nf = 0; nf < 4; nf++) {
                    mma16816(acc[mf][nf][0], acc[mf][nf][1],
                             acc[mf][nf][2], acc[mf][nf][3],
                             a0, a1, a2, a3, b0[nf], b1[nf]);
                }
            }
        }
        __syncthreads();
    }

    // ---- epilogue: +bias, store into g_Gx[t][n>>4][b][n&15] ----
#pragma unroll
    for (int nf = 0; nf < 4; nf++) {
        const int n = n0 + warpN + nf * 8 + tig * 2;
        const float bi0 = g_bpack[n];
        const float bi1 = g_bpack[n + 1];
        const size_t ncol = ((size_t)(n >> 4)) * 1024 + (size_t)(n & 15);
#pragma unroll
        for (int mf = 0; mf < 4; mf++) {
            const int m = m0 + warpM + mf * 16 + groupid;
            {
                const int t = m >> 6, b = m & 63;
                float2 v;
                v.x = acc[mf][nf][0] + bi0;
                v.y = acc[mf][nf][1] + bi1;
                *(float2*)(g_Gx + (size_t)t * 131072 + ncol + (size_t)b * 16) = v;
            }
            {
                const int m2 = m + 8;
                const int t = m2 >> 6, b = m2 & 63;
                float2 v;
                v.x = acc[mf][nf][2] + bi0;
                v.y = acc[mf][nf][3] + bi1;
                *(float2*)(g_Gx + (size_t)t * 131072 + ncol + (size_t)b * 16) = v;
            }
        }
    }
}

// ============================================================================
// Phase 2: persistent sequential LSTM (round-10 passing kernel, verbatim).
// ============================================================================
#define SM_WH   0
#define SM_H    65536
#define SM_PART (65536 + 131072)
#define SM_GX   (SM_PART + 4096 * 4)
#define SM_HS   (SM_GX + 1024 * 4)
#define SM_TOT  (SM_HS + 256 * 4)

__device__ __forceinline__ void grid_bar(unsigned target) {
    __threadfence();
    __syncthreads();
    if (threadIdx.x == 0) {
        atomicAdd(&g_bar, 1u);
        while (*(volatile unsigned*)&g_bar < target) {}
        __threadfence();
    }
    __syncthreads();
}

__global__ void __launch_bounds__(256, 1)
qlstm_seq(float* __restrict__ out) {
    extern __shared__ char smraw[];
    ull* sWh2 = (ull*)(smraw + SM_WH);
    float* sH = (float*)(smraw + SM_H);
    float* sPart = (float*)(smraw + SM_PART);
    float* sGx = (float*)(smraw + SM_GX);
    float* sHs = (float*)(smraw + SM_HS);

    const int tid = threadIdx.x;
    const int cta = blockIdx.x;

    for (int i = tid; i < 16 * HID; i += 256)
        sWh2[i] = pack2(g_Whp[(size_t)cta * 16 * HID + i]);

    const int wrp = tid >> 5;
    const int lane = tid & 31;
    const int kq = wrp >> 1;
    const int r0 = (wrp & 1) * 8;
    const int k0 = kq * 128;
    const ull* wbase = sWh2 + r0 * HID + k0;
    const ull* sHu = (const ull*)sH;

    const int jl = tid >> 6;
    const int b = tid & 63;
    const int jg = cta * 4 + jl;
    float c_state = 0.0f;
    float h_val = 0.0f;

    __syncthreads();

    for (int t = 0; t < SEQ; t++) {
        if (t > 0 && tid < 64) {
            float4 hv = *(float4*)&sHs[tid * 4];
            *(float4*)(out + (size_t)((t - 1) * BATCH + tid) * HID + cta * 4) = hv;
        }

        ((float4*)sGx)[tid] =
            ((const float4*)g_Gx)[((size_t)t * 128 + cta) * 256 + tid];

        if (t > 0) {
            const float4* src = (const float4*)(g_hT + ((t - 1) & 1) * (HID * BATCH));
#pragma unroll 4
            for (int i = tid; i < HID * BATCH / 4; i += 256)
                ((float4*)sH)[i] = __ldcv(src + i);
            __syncthreads();

            ull a[8];
#pragma unroll
            for (int r = 0; r < 8; r++) a[r] = 0ull;
#pragma unroll 2
            for (int kk = 0; kk < 128; kk += 2) {
                ull h0 = sHu[(k0 + kk) * 32 + lane];
                ull h1 = sHu[(k0 + kk + 1) * 32 + lane];
#pragma unroll
                for (int r = 0; r < 8; r++) {
                    ulonglong2 wv = *(const ulonglong2*)(wbase + r * HID + kk);
                    ffma2(a[r], wv.x, h0);
                    ffma2(a[r], wv.y, h1);
                }
            }
#pragma unroll
            for (int r = 0; r < 8; r++)
                *(ull*)&sPart[((kq * 16) + r0 + r) * 64 + 2 * lane] = a[r];
            __syncthreads();
        } else {
            __syncthreads();
        }

        float pre[4];
#pragma unroll
        for (int g = 0; g < 4; g++) {
            float s = sGx[b * 16 + jl * 4 + g];
            if (t > 0) {
#pragma unroll
                for (int q = 0; q < 4; q++)
                    s += sPart[(q * 16 + jl * 4 + g) * 64 + b];
            }
            pre[g] = s;
        }
        float fg = sigmoidf_(pre[0]);
        float ig = sigmoidf_(pre[1]);
        float gg = tanhf_(pre[2]);
        float og = sigmoidf_(pre[3]);
        c_state = fg * c_state + ig * gg;
        h_val = og * tanhf_(c_state);

        g_hT[(t & 1) * (HID * BATCH) + jg * BATCH + b] = h_val;
        sHs[b * 4 + jl] = h_val;

        grid_bar(128u * (unsigned)(t + 1));
    }

    if (tid < 64) {
        float4 hv = *(float4*)&sHs[tid * 4];
        *(float4*)(out + (size_t)((SEQ - 1) * BATCH + tid) * HID + cta * 4) = hv;
    }
    const size_t off = (size_t)SEQ * BATCH * HID;
    out[off + (size_t)b * HID + jg] = h_val;
    out[off + (size_t)BATCH * HID + (size_t)b * HID + jg] = c_state;
}

// ============================================================================
extern "C" void kernel_launch(void* const* d_in, const int* in_sizes, int n_in,
                              void* d_out, int out_size) {
    const float* x = (const float*)d_in[0];
    const float* Wf = (const float*)d_in[1];
    const float* bf = (const float*)d_in[2];
    const float* Wi = (const float*)d_in[3];
    const float* bi = (const float*)d_in[4];
    const float* Wg = (const float*)d_in[5];
    const float* bg = (const float*)d_in[6];
    const float* Wo = (const float*)d_in[7];
    const float* bo = (const float*)d_in[8];
    float* out = (float*)d_out;

    qlstm_reset<<<1, 32>>>();
    qlstm_pack<<<256, 256>>>(Wf, bf, Wi, bi, Wg, bg, Wo, bo);
    qlstm_splitx<<<1024, 256>>>(x);

    cudaFuncSetAttribute(qlstm_gemm_mma,
                         cudaFuncAttributeMaxDynamicSharedMemorySize, P1_SMEM);
    dim3 g1(16, 1024);
    qlstm_gemm_mma<<<g1, 256, P1_SMEM>>>();

    cudaFuncSetAttribute(qlstm_seq,
                         cudaFuncAttributeMaxDynamicSharedMemorySize, SM_TOT);
    qlstm_seq<<<128, 256, SM_TOT>>>(out);
}